// round 6
// baseline (speedup 1.0000x reference)
#include <cuda_runtime.h>

// CGCoupler: out[n, ro[m]] += x1[n, r1[m]] * x2[n, r2[m]] * cg[m]
//
// Paths: index arrays are path-major runs (r1/r2/ro consecutive, cg equal) over
// a dense channel dim ns=0..deg-1.
// prep1 (grid-parallel): extract paths {r1_0,r2_0,cg,deg,ro_0} into an
//   unordered list (atomic counter).
// prep2 (1 CTA): bin by ro_0, prefix scan, scatter, canonical in-bin sort
//   (deg desc, r1 asc, r2 asc) -> deterministic, and per-column
//   {start|ns<<16, eff} with eff = #paths of that bin with deg > ns.
// couple (persistent, double-buffered): thread owns 2 columns (tid, tid+TPB),
//   fused inner loop for ILP; x tiles staged 4-rows-interleaved as float4 so
//   gathers are lane-consecutive LDS.128 (conflict-free); staging of the next
//   tile overlaps compute of the current one through the back smem buffer.

#define N_BATCH 16384
#define RPT     4
#define TPB     320
#define MAX_P   4096
#define MAX_OUT 2048
#define P_SMEM  512
#define NSM     148
#define OCC     4

__device__ uint4 g_plist[MAX_P];      // unordered {r1_0, r2_0, cg_bits, deg}
__device__ int   g_pro[MAX_P];
__device__ int   g_np = 0;            // prep1 accumulates; prep2 resets to 0
__device__ int   g_npf = 0;
__device__ uint4 g_paths[MAX_P];      // binned + canonically sorted
__device__ uint2 g_colinfo[MAX_OUT];  // {start | ns<<16, eff}

__device__ __forceinline__ int block_incl_scan(int v, int tid) {
    __shared__ int ws[32];
    int lane = tid & 31, wid = tid >> 5;
    __syncthreads();
    #pragma unroll
    for (int d = 1; d < 32; d <<= 1) {
        int t = __shfl_up_sync(0xffffffffu, v, d);
        if (lane >= d) v += t;
    }
    if (lane == 31) ws[wid] = v;
    __syncthreads();
    if (wid == 0) {
        int w = ws[lane];
        #pragma unroll
        for (int d = 1; d < 32; d <<= 1) {
            int t = __shfl_up_sync(0xffffffffu, w, d);
            if (lane >= d) w += t;
        }
        ws[lane] = w;
    }
    __syncthreads();
    return v + (wid > 0 ? ws[wid - 1] : 0);
}

__global__ void prep1_kernel(const void* r1v, const void* r2v, const void* rov,
                             const float* __restrict__ cg, int M) {
    __shared__ int s_is64;
    int tid = threadIdx.x;
    // dtype auto-detect: int64 little-endian small values -> odd words zero.
    // Scan only the first min(M,2048) 32-bit words (always in-bounds).
    if (tid < 32) {
        const unsigned* w = (const unsigned*)r1v;
        int nw = M < 2048 ? M : 2048;
        int bad = 0;
        for (int i = 1 + 2 * tid; i < nw; i += 64) bad |= (w[i] != 0u);
        unsigned any = __ballot_sync(0xffffffffu, bad != 0);
        if (tid == 0) s_is64 = (any == 0u);
    }
    __syncthreads();
    int is64 = s_is64;
    const int*       r132 = (const int*)r1v;  const long long* r164 = (const long long*)r1v;
    const int*       r232 = (const int*)r2v;  const long long* r264 = (const long long*)r2v;
    const int*       ro32 = (const int*)rov;  const long long* ro64 = (const long long*)rov;
    const unsigned*  cgu  = (const unsigned*)cg;
    #define IDX1(m) (is64 ? (int)r164[m] : r132[m])
    #define IDX2(m) (is64 ? (int)r264[m] : r232[m])
    #define IDXO(m) (is64 ? (int)ro64[m] : ro32[m])

    int gs = blockDim.x * gridDim.x;
    for (int m = blockIdx.x * blockDim.x + tid; m < M; m += gs) {
        int a = IDX1(m), b = IDX2(m), o = IDXO(m);
        unsigned cgm = cgu[m];
        bool start = (m == 0) ||
            !(IDX1(m - 1) + 1 == a && IDX2(m - 1) + 1 == b &&
              IDXO(m - 1) + 1 == o && cgu[m - 1] == cgm);
        if (start) {
            int deg = 1;
            while (m + deg < M && IDX1(m + deg) == a + deg && IDX2(m + deg) == b + deg &&
                   IDXO(m + deg) == o + deg && cgu[m + deg] == cgm) deg++;
            int pos = atomicAdd(&g_np, 1);
            if (pos < MAX_P) {
                g_plist[pos] = make_uint4((unsigned)a, (unsigned)b, cgm, (unsigned)deg);
                g_pro[pos]   = o;
            }
        }
    }
    #undef IDX1
    #undef IDX2
    #undef IDXO
}

__global__ void prep2_kernel(int out_dim) {
    __shared__ int cnt[MAX_OUT], stt[MAX_OUT], cur[MAX_OUT];
    int tid = threadIdx.x, bd = blockDim.x;
    int P = g_np;
    for (int i = tid; i < out_dim; i += bd) cnt[i] = 0;
    __syncthreads();
    for (int p = tid; p < P; p += bd) atomicAdd(&cnt[g_pro[p]], 1);
    __syncthreads();
    // exclusive scan of cnt -> stt (chunked)
    int CH = (out_dim + bd - 1) / bd;
    int cb = tid * CH;
    int local = 0;
    for (int i = 0; i < CH; i++) { int idx = cb + i; if (idx < out_dim) local += cnt[idx]; }
    int incl = block_incl_scan(local, tid);
    int run = incl - local;
    for (int i = 0; i < CH; i++) {
        int idx = cb + i;
        if (idx < out_dim) { stt[idx] = run; cur[idx] = run; run += cnt[idx]; }
    }
    __syncthreads();
    for (int p = tid; p < P; p += bd) {
        int pos = atomicAdd(&cur[g_pro[p]], 1);
        g_paths[pos] = g_plist[p];
    }
    __syncthreads();
    // canonical in-bin insertion sort: deg DESC, r1 ASC, r2 ASC (unique key)
    for (int b = tid; b < out_dim; b += bd) {
        int c0 = cnt[b];
        if (c0 > 1) {
            int s0 = stt[b];
            for (int i = 1; i < c0; i++) {
                uint4 key = g_paths[s0 + i];
                int j = i - 1;
                while (j >= 0) {
                    uint4 q = g_paths[s0 + j];
                    bool keyFirst = (key.w > q.w) ||
                                    (key.w == q.w && (key.x < q.x ||
                                     (key.x == q.x && key.y < q.y)));
                    if (!keyFirst) break;
                    g_paths[s0 + j + 1] = q;
                    j--;
                }
                g_paths[s0 + j + 1] = key;
            }
        }
    }
    __syncthreads();
    for (int c = tid; c < out_dim; c += bd) {
        int b = c;
        while (b >= 0 && cnt[b] == 0) b--;
        uint2 info = make_uint2(0u, 0u);
        if (b >= 0) {
            int c0 = cnt[b], s0 = stt[b], ns = c - b, eff = 0;
            while (eff < c0 && (int)g_paths[s0 + eff].w > ns) eff++;
            if (eff > 0)
                info = make_uint2((unsigned)s0 | ((unsigned)ns << 16), (unsigned)eff);
        }
        g_colinfo[c] = info;
    }
    if (tid == 0) { g_npf = P; g_np = 0; }
}

__global__ void __launch_bounds__(TPB, OCC)
couple_kernel(const float* __restrict__ x1, const float* __restrict__ x2,
              float* __restrict__ out, int rep_dim, int out_dim, int ntiles) {
    extern __shared__ char smraw[];
    float4* bufs = (float4*)smraw;                        // [2][2*rep_dim] float4
    uint2*  ci   = (uint2*)(bufs + 4 * (size_t)rep_dim);  // out_dim
    uint4*  pts  = (uint4*)(ci + ((out_dim + 1) & ~1));   // P_SMEM paths

    int tid = threadIdx.x;
    int P = g_npf;
    int pl = P < P_SMEM ? P : P_SMEM;
    for (int i = tid; i < pl; i += TPB) pts[i] = g_paths[i];
    for (int i = tid; i < out_dim; i += TPB) ci[i] = g_colinfo[i];
    const uint4* pp = (P <= P_SMEM) ? (const uint4*)pts : (const uint4*)g_paths;

    int t = blockIdx.x;
    int stride = gridDim.x;

    // stage first tile into phase 0
    if (t < ntiles) {
        const float* a0 = x1 + (size_t)t * RPT * rep_dim;
        const float* b0 = x2 + (size_t)t * RPT * rep_dim;
        for (int i = tid; i < rep_dim; i += TPB) {
            bufs[i] = make_float4(a0[i], a0[i + rep_dim], a0[i + 2 * rep_dim], a0[i + 3 * rep_dim]);
            bufs[rep_dim + i] = make_float4(b0[i], b0[i + rep_dim], b0[i + 2 * rep_dim], b0[i + 3 * rep_dim]);
        }
    }
    __syncthreads();

    // hoisted per-thread column info (tile-invariant); fast path: out_dim <= 2*TPB
    int o0 = tid, o1 = tid + TPB;
    uint2 c0 = (o0 < out_dim) ? ci[o0] : make_uint2(0u, 0u);
    uint2 c1 = (o1 < out_dim) ? ci[o1] : make_uint2(0u, 0u);
    int s0 = (int)(c0.x & 0xffffu), ne0 = (int)c0.y; unsigned ns0 = c0.x >> 16;
    int s1 = (int)(c1.x & 0xffffu), ne1 = (int)c1.y; unsigned ns1 = c1.x >> 16;
    int nm = ne0 > ne1 ? ne0 : ne1;

    int phase = 0;
    for (; t < ntiles; t += stride) {
        float4* curb = bufs + phase * 2 * (size_t)rep_dim;
        float4* nxtb = bufs + (phase ^ 1) * 2 * (size_t)rep_dim;
        int tn = t + stride;
        // stage next tile into back buffer (no barrier: overlaps compute below)
        if (tn < ntiles) {
            const float* a0 = x1 + (size_t)tn * RPT * rep_dim;
            const float* b0 = x2 + (size_t)tn * RPT * rep_dim;
            for (int i = tid; i < rep_dim; i += TPB) {
                nxtb[i] = make_float4(a0[i], a0[i + rep_dim], a0[i + 2 * rep_dim], a0[i + 3 * rep_dim]);
                nxtb[rep_dim + i] = make_float4(b0[i], b0[i + rep_dim], b0[i + 2 * rep_dim], b0[i + 3 * rep_dim]);
            }
        }

        const float4* x1s = curb;
        const float4* x2s = curb + rep_dim;
        float4 acc0 = make_float4(0.f, 0.f, 0.f, 0.f);
        float4 acc1 = make_float4(0.f, 0.f, 0.f, 0.f);
        for (int j = 0; j < nm; j++) {
            if (j < ne0) {
                uint4 p = pp[s0 + j];                // warp-uniform: broadcast
                float cgv = __uint_as_float(p.z);
                float4 A = x1s[p.x + ns0];           // lane-consecutive: conflict-free
                float4 B = x2s[p.y + ns0];
                acc0.x = fmaf(A.x * B.x, cgv, acc0.x);
                acc0.y = fmaf(A.y * B.y, cgv, acc0.y);
                acc0.z = fmaf(A.z * B.z, cgv, acc0.z);
                acc0.w = fmaf(A.w * B.w, cgv, acc0.w);
            }
            if (j < ne1) {
                uint4 p = pp[s1 + j];
                float cgv = __uint_as_float(p.z);
                float4 A = x1s[p.x + ns1];
                float4 B = x2s[p.y + ns1];
                acc1.x = fmaf(A.x * B.x, cgv, acc1.x);
                acc1.y = fmaf(A.y * B.y, cgv, acc1.y);
                acc1.z = fmaf(A.z * B.z, cgv, acc1.z);
                acc1.w = fmaf(A.w * B.w, cgv, acc1.w);
            }
        }
        int r = t * RPT;
        if (o0 < out_dim) {
            float* ob = out + (size_t)r * out_dim + o0;
            ob[0] = acc0.x; ob[out_dim] = acc0.y;
            ob[2 * (size_t)out_dim] = acc0.z; ob[3 * (size_t)out_dim] = acc0.w;
        }
        if (o1 < out_dim) {
            float* ob = out + (size_t)r * out_dim + o1;
            ob[0] = acc1.x; ob[out_dim] = acc1.y;
            ob[2 * (size_t)out_dim] = acc1.z; ob[3 * (size_t)out_dim] = acc1.w;
        }
        // generic fallback for out_dim > 2*TPB (not taken for this shape)
        for (int obase = 2 * TPB; obase < out_dim; obase += TPB) {
            int o = obase + tid;
            if (o < out_dim) {
                uint2 c = ci[o];
                int s = (int)(c.x & 0xffffu), ne = (int)c.y;
                unsigned ns = c.x >> 16;
                float4 acc = make_float4(0.f, 0.f, 0.f, 0.f);
                for (int j = 0; j < ne; j++) {
                    uint4 p = pp[s + j];
                    float cgv = __uint_as_float(p.z);
                    float4 A = x1s[p.x + ns];
                    float4 B = x2s[p.y + ns];
                    acc.x = fmaf(A.x * B.x, cgv, acc.x);
                    acc.y = fmaf(A.y * B.y, cgv, acc.y);
                    acc.z = fmaf(A.z * B.z, cgv, acc.z);
                    acc.w = fmaf(A.w * B.w, cgv, acc.w);
                }
                float* ob = out + (size_t)r * out_dim + o;
                ob[0] = acc.x; ob[out_dim] = acc.y;
                ob[2 * (size_t)out_dim] = acc.z; ob[3 * (size_t)out_dim] = acc.w;
            }
        }
        __syncthreads();   // back buffer fully staged, current buffer consumed
        phase ^= 1;
    }
}

extern "C" void kernel_launch(void* const* d_in, const int* in_sizes, int n_in,
                              void* d_out, int out_size) {
    const float* x1 = (const float*)d_in[0];
    const float* x2 = (const float*)d_in[1];
    const float* cg = (const float*)d_in[2];
    const void*  r1 = d_in[3];
    const void*  r2 = d_in[4];
    const void*  ro = d_in[5];
    int M = in_sizes[2];
    int rep_dim = in_sizes[0] / N_BATCH;
    int out_dim = out_size / N_BATCH;
    int ntiles  = N_BATCH / RPT;

    prep1_kernel<<<32, 256>>>(r1, r2, ro, cg, M);
    prep2_kernel<<<1, 1024>>>(out_dim);

    size_t smem = (size_t)rep_dim * 64 + (size_t)((out_dim + 1) & ~1) * 8
                + (size_t)P_SMEM * 16;
    cudaFuncSetAttribute(couple_kernel,
                         cudaFuncAttributeMaxDynamicSharedMemorySize, 220 * 1024);
    int grid = NSM * OCC;
    if (grid > ntiles) grid = ntiles;
    couple_kernel<<<grid, TPB, smem>>>(x1, x2, (float*)d_out,
                                       rep_dim, out_dim, ntiles);
}

// round 7
// speedup vs baseline: 1.0263x; 1.0263x over previous
#include <cuda_runtime.h>

// CGCoupler: out[n, ro[m]] += x1[n, r1[m]] * x2[n, r2[m]] * cg[m]
//
// Paths: index arrays are path-major runs (r1/r2/ro consecutive, cg equal) over
// a dense channel dim ns=0..deg-1. Run starts partition [0,M), so
// deg_i = start_{i+1} - start_i  -- no serial run walking anywhere.
// prep1 (grid-parallel): flag run starts, compact positions (atomic, unordered).
// prep2 (1 CTA, smem-resident): bitonic-sort positions, degs by difference,
//   bin paths by output base ro_0, prefix scan, scatter, canonical in-bin sort
//   (deg desc, r1 asc, r2 asc) -> fully deterministic; per-column
//   {start|ns<<16, eff} with eff = #paths in bin with deg > ns.
// couple (persistent, occupancy-first): 5 CTAs/SM, thread owns 2 columns
//   (tid, tid+TPB); x tiles staged 4-rows-interleaved as float4 so gathers are
//   lane-consecutive LDS.128 (conflict-free); path records broadcast from smem.

#define N_BATCH 16384
#define RPT     4
#define TPB     320
#define OCC     5
#define NSM     148
#define MAX_P   4096
#define MAX_OUT 2048
#define P_SMEM  512
#define NSORT   512

__device__ int   g_spos[MAX_P];       // unordered run-start positions
__device__ int   g_np = 0;            // prep1 accumulates; prep2 resets to 0
__device__ uint4 g_paths[MAX_P];      // binned + canonically sorted {r1,r2,cg,deg}
__device__ uint2 g_colinfo[MAX_OUT];  // {start | ns<<16, eff}

__device__ __forceinline__ int block_incl_scan(int v, int tid) {
    __shared__ int ws[32];
    int lane = tid & 31, wid = tid >> 5;
    __syncthreads();
    #pragma unroll
    for (int d = 1; d < 32; d <<= 1) {
        int t = __shfl_up_sync(0xffffffffu, v, d);
        if (lane >= d) v += t;
    }
    if (lane == 31) ws[wid] = v;
    __syncthreads();
    if (wid == 0) {
        int w = ws[lane];
        #pragma unroll
        for (int d = 1; d < 32; d <<= 1) {
            int t = __shfl_up_sync(0xffffffffu, w, d);
            if (lane >= d) w += t;
        }
        ws[lane] = w;
    }
    __syncthreads();
    return v + (wid > 0 ? ws[wid - 1] : 0);
}

__device__ __forceinline__ int detect_is64(const void* r1v, int M) {
    // int64 little-endian small values -> odd 32-bit words all zero
    const unsigned* w = (const unsigned*)r1v;
    int nw = M < 512 ? M : 512;
    int lane = threadIdx.x & 31;
    int bad = 0;
    for (int i = 1 + 2 * lane; i < nw; i += 64) bad |= (w[i] != 0u);
    return __ballot_sync(0xffffffffu, bad != 0) == 0u;
}

__global__ void prep1_kernel(const void* r1v, const void* r2v, const void* rov,
                             const float* __restrict__ cg, int M) {
    int is64 = detect_is64(r1v, M);
    const int*       r132 = (const int*)r1v;  const long long* r164 = (const long long*)r1v;
    const int*       r232 = (const int*)r2v;  const long long* r264 = (const long long*)r2v;
    const int*       ro32 = (const int*)rov;  const long long* ro64 = (const long long*)rov;
    const unsigned*  cgu  = (const unsigned*)cg;
    #define IDX1(m) (is64 ? (int)r164[m] : r132[m])
    #define IDX2(m) (is64 ? (int)r264[m] : r232[m])
    #define IDXO(m) (is64 ? (int)ro64[m] : ro32[m])
    int gs = blockDim.x * gridDim.x;
    for (int m = blockIdx.x * blockDim.x + threadIdx.x; m < M; m += gs) {
        bool start = (m == 0) ||
            !(IDX1(m - 1) + 1 == IDX1(m) && IDX2(m - 1) + 1 == IDX2(m) &&
              IDXO(m - 1) + 1 == IDXO(m) && cgu[m - 1] == cgu[m]);
        if (start) {
            int pos = atomicAdd(&g_np, 1);
            if (pos < MAX_P) g_spos[pos] = m;
        }
    }
    #undef IDX1
    #undef IDX2
    #undef IDXO
}

__global__ void prep2_kernel(const void* r1v, const void* r2v, const void* rov,
                             const float* __restrict__ cg, int M, int out_dim) {
    __shared__ int sp[NSORT];
    __shared__ int cnt[MAX_OUT], stt[MAX_OUT], cur[MAX_OUT];
    int tid = threadIdx.x, bd = blockDim.x;
    int is64 = detect_is64(r1v, M);
    const int*       r132 = (const int*)r1v;  const long long* r164 = (const long long*)r1v;
    const int*       r232 = (const int*)r2v;  const long long* r264 = (const long long*)r2v;
    const int*       ro32 = (const int*)rov;  const long long* ro64 = (const long long*)rov;
    const unsigned*  cgu  = (const unsigned*)cg;
    #define IDX1(m) (is64 ? (int)r164[m] : r132[m])
    #define IDX2(m) (is64 ? (int)r264[m] : r232[m])
    #define IDXO(m) (is64 ? (int)ro64[m] : ro32[m])

    int P = g_np;
    if (P > NSORT) P = NSORT;                  // safety; expected P ~ 150
    for (int i = tid; i < NSORT; i += bd) sp[i] = (i < P) ? g_spos[i] : M;
    // bitonic sort ascending (sentinels = M stay at the tail)
    for (int k = 2; k <= NSORT; k <<= 1) {
        for (int j = k >> 1; j > 0; j >>= 1) {
            __syncthreads();
            for (int i = tid; i < NSORT; i += bd) {
                int ixj = i ^ j;
                if (ixj > i) {
                    bool up = ((i & k) == 0);
                    int a = sp[i], b = sp[ixj];
                    if ((a > b) == up) { sp[i] = b; sp[ixj] = a; }
                }
            }
        }
    }
    __syncthreads();

    for (int i = tid; i < out_dim; i += bd) cnt[i] = 0;
    __syncthreads();
    // bin counts (paths now in canonical position order; sp[i+1] valid: sp[P]=M)
    for (int p = tid; p < P; p += bd) atomicAdd(&cnt[IDXO(sp[p])], 1);
    __syncthreads();
    // exclusive scan of cnt -> stt
    int CH = (out_dim + bd - 1) / bd;
    int cb = tid * CH;
    int local = 0;
    for (int i = 0; i < CH; i++) { int idx = cb + i; if (idx < out_dim) local += cnt[idx]; }
    int incl = block_incl_scan(local, tid);
    int run = incl - local;
    for (int i = 0; i < CH; i++) {
        int idx = cb + i;
        if (idx < out_dim) { stt[idx] = run; cur[idx] = run; run += cnt[idx]; }
    }
    __syncthreads();
    // scatter paths into bins
    for (int p = tid; p < P; p += bd) {
        int s = sp[p];
        int deg = sp[p + 1] - s;
        int o = IDXO(s);
        int pos = atomicAdd(&cur[o], 1);
        g_paths[pos] = make_uint4((unsigned)IDX1(s), (unsigned)IDX2(s),
                                  cgu[s], (unsigned)deg);
    }
    __syncthreads();
    // canonical in-bin insertion sort: deg DESC, r1 ASC, r2 ASC (unique key)
    for (int b = tid; b < out_dim; b += bd) {
        int c0 = cnt[b];
        if (c0 > 1) {
            int s0 = stt[b];
            for (int i = 1; i < c0; i++) {
                uint4 key = g_paths[s0 + i];
                int j = i - 1;
                while (j >= 0) {
                    uint4 q = g_paths[s0 + j];
                    bool keyFirst = (key.w > q.w) ||
                                    (key.w == q.w && (key.x < q.x ||
                                     (key.x == q.x && key.y < q.y)));
                    if (!keyFirst) break;
                    g_paths[s0 + j + 1] = q;
                    j--;
                }
                g_paths[s0 + j + 1] = key;
            }
        }
    }
    __syncthreads();
    for (int c = tid; c < out_dim; c += bd) {
        int b = c;
        while (b >= 0 && cnt[b] == 0) b--;
        uint2 info = make_uint2(0u, 0u);
        if (b >= 0) {
            int c0 = cnt[b], s0 = stt[b], ns = c - b, eff = 0;
            while (eff < c0 && (int)g_paths[s0 + eff].w > ns) eff++;
            if (eff > 0)
                info = make_uint2((unsigned)s0 | ((unsigned)ns << 16), (unsigned)eff);
        }
        g_colinfo[c] = info;
    }
    if (tid == 0) g_np = 0;                    // rearm for next graph replay
    #undef IDX1
    #undef IDX2
    #undef IDXO
}

__global__ void __launch_bounds__(TPB, OCC)
couple_kernel(const float* __restrict__ x1, const float* __restrict__ x2,
              float* __restrict__ out, int rep_dim, int out_dim, int ntiles) {
    extern __shared__ char smraw[];
    float4* x1s = (float4*)smraw;                       // rep_dim (4 rows interleaved)
    float4* x2s = x1s + rep_dim;
    uint2*  ci  = (uint2*)(x2s + rep_dim);              // out_dim
    uint4*  pts = (uint4*)(ci + ((out_dim + 1) & ~1));  // P_SMEM paths

    int tid = threadIdx.x;
    for (int i = tid; i < P_SMEM; i += TPB) pts[i] = g_paths[i];
    for (int i = tid; i < out_dim; i += TPB) ci[i] = g_colinfo[i];

    // hoisted per-thread column info; thread reads exactly the ci entries it
    // wrote (i = tid, tid+TPB) so no barrier needed here.
    int o0 = tid, o1 = tid + TPB;
    uint2 c0 = (o0 < out_dim) ? ci[o0] : make_uint2(0u, 0u);
    uint2 c1 = (o1 < out_dim) ? ci[o1] : make_uint2(0u, 0u);
    int s0 = (int)(c0.x & 0xffffu), ne0 = (int)c0.y; unsigned ns0 = c0.x >> 16;
    int s1 = (int)(c1.x & 0xffffu), ne1 = (int)c1.y; unsigned ns1 = c1.x >> 16;

    for (int t = blockIdx.x; t < ntiles; t += gridDim.x) {
        __syncthreads();   // prior tile fully consumed (and 1st iter: pts ready)
        {
            const float* a0 = x1 + (size_t)t * RPT * rep_dim;
            const float* b0 = x2 + (size_t)t * RPT * rep_dim;
            for (int i = tid; i < rep_dim; i += TPB) {
                x1s[i] = make_float4(a0[i], a0[i + rep_dim],
                                     a0[i + 2 * rep_dim], a0[i + 3 * rep_dim]);
                x2s[i] = make_float4(b0[i], b0[i + rep_dim],
                                     b0[i + 2 * rep_dim], b0[i + 3 * rep_dim]);
            }
        }
        __syncthreads();

        float4 acc0 = make_float4(0.f, 0.f, 0.f, 0.f);
        float4 acc1 = make_float4(0.f, 0.f, 0.f, 0.f);
        #pragma unroll 2
        for (int j = 0; j < ne0; j++) {
            uint4 p = pts[s0 + j];               // warp-uniform: broadcast
            float cgv = __uint_as_float(p.z);
            float4 A = x1s[p.x + ns0];           // lane-consecutive: conflict-free
            float4 B = x2s[p.y + ns0];
            acc0.x = fmaf(A.x * B.x, cgv, acc0.x);
            acc0.y = fmaf(A.y * B.y, cgv, acc0.y);
            acc0.z = fmaf(A.z * B.z, cgv, acc0.z);
            acc0.w = fmaf(A.w * B.w, cgv, acc0.w);
        }
        #pragma unroll 2
        for (int j = 0; j < ne1; j++) {
            uint4 p = pts[s1 + j];
            float cgv = __uint_as_float(p.z);
            float4 A = x1s[p.x + ns1];
            float4 B = x2s[p.y + ns1];
            acc1.x = fmaf(A.x * B.x, cgv, acc1.x);
            acc1.y = fmaf(A.y * B.y, cgv, acc1.y);
            acc1.z = fmaf(A.z * B.z, cgv, acc1.z);
            acc1.w = fmaf(A.w * B.w, cgv, acc1.w);
        }
        int r = t * RPT;
        if (o0 < out_dim) {
            float* ob = out + (size_t)r * out_dim + o0;
            ob[0] = acc0.x; ob[out_dim] = acc0.y;
            ob[2 * (size_t)out_dim] = acc0.z; ob[3 * (size_t)out_dim] = acc0.w;
        }
        if (o1 < out_dim) {
            float* ob = out + (size_t)r * out_dim + o1;
            ob[0] = acc1.x; ob[out_dim] = acc1.y;
            ob[2 * (size_t)out_dim] = acc1.z; ob[3 * (size_t)out_dim] = acc1.w;
        }
        // generic fallback for out_dim > 2*TPB (not taken for this shape)
        for (int obase = 2 * TPB; obase < out_dim; obase += TPB) {
            int o = obase + tid;
            if (o < out_dim) {
                uint2 c = ci[o];
                int s = (int)(c.x & 0xffffu), ne = (int)c.y;
                unsigned ns = c.x >> 16;
                float4 acc = make_float4(0.f, 0.f, 0.f, 0.f);
                for (int j = 0; j < ne; j++) {
                    uint4 p = pts[s + j];
                    float cgv = __uint_as_float(p.z);
                    float4 A = x1s[p.x + ns];
                    float4 B = x2s[p.y + ns];
                    acc.x = fmaf(A.x * B.x, cgv, acc.x);
                    acc.y = fmaf(A.y * B.y, cgv, acc.y);
                    acc.z = fmaf(A.z * B.z, cgv, acc.z);
                    acc.w = fmaf(A.w * B.w, cgv, acc.w);
                }
                float* ob = out + (size_t)r * out_dim + o;
                ob[0] = acc.x; ob[out_dim] = acc.y;
                ob[2 * (size_t)out_dim] = acc.z; ob[3 * (size_t)out_dim] = acc.w;
            }
        }
    }
}

extern "C" void kernel_launch(void* const* d_in, const int* in_sizes, int n_in,
                              void* d_out, int out_size) {
    const float* x1 = (const float*)d_in[0];
    const float* x2 = (const float*)d_in[1];
    const float* cg = (const float*)d_in[2];
    const void*  r1 = d_in[3];
    const void*  r2 = d_in[4];
    const void*  ro = d_in[5];
    int M = in_sizes[2];
    int rep_dim = in_sizes[0] / N_BATCH;
    int out_dim = out_size / N_BATCH;
    int ntiles  = N_BATCH / RPT;

    prep1_kernel<<<64, 256>>>(r1, r2, ro, cg, M);
    prep2_kernel<<<1, 512>>>(r1, r2, ro, cg, M, out_dim);

    size_t smem = (size_t)rep_dim * 32 + (size_t)((out_dim + 1) & ~1) * 8
                + (size_t)P_SMEM * 16;
    cudaFuncSetAttribute(couple_kernel,
                         cudaFuncAttributeMaxDynamicSharedMemorySize, 220 * 1024);
    int grid = NSM * OCC;
    if (grid > ntiles) grid = ntiles;
    couple_kernel<<<grid, TPB, smem>>>(x1, x2, (float*)d_out,
                                       rep_dim, out_dim, ntiles);
}

// round 9
// speedup vs baseline: 1.0935x; 1.0655x over previous
#include <cuda_runtime.h>

// CGCoupler: out[n, ro[m]] += x1[n, r1[m]] * x2[n, r2[m]] * cg[m]
//
// Paths: index arrays are path-major runs (r1/r2/ro consecutive, cg equal) over
// a dense channel dim ns=0..deg-1. Run starts partition [0,M):
// deg_i = start_{i+1} - start_i.
// prep (ONE kernel, 1 CTA, smem-resident): ordered compaction of run starts via
//   chunked block scan (order-preserving -> deterministic, no sort of positions),
//   bin by output base ro_0, prefix scan, scatter, canonical in-bin insertion
//   sort (deg desc, r1 asc, r2 asc) ALL IN SHARED MEMORY, then one coalesced
//   write-out of g_paths (zero-padded) + g_colinfo.
// couple (persistent, occupancy-first): 5 CTAs/SM, thread owns 2 columns
//   (tid, tid+TPB); x tiles staged 4-rows-interleaved as float4 so gathers are
//   lane-consecutive LDS.128 (conflict-free); path records broadcast from smem.

#define N_BATCH 16384
#define RPT     4
#define TPB     320
#define OCC     5
#define NSM     148
#define MAX_OUT 2048
#define P_SMEM  512
#define NSORT   512

__device__ uint4 g_paths[P_SMEM];     // binned + canonically sorted {r1,r2,cg,deg}
__device__ uint2 g_colinfo[MAX_OUT];  // {start | ns<<16, eff}

__device__ __forceinline__ int block_incl_scan(int v, int tid) {
    __shared__ int ws[32];
    int lane = tid & 31, wid = tid >> 5;
    __syncthreads();
    #pragma unroll
    for (int d = 1; d < 32; d <<= 1) {
        int t = __shfl_up_sync(0xffffffffu, v, d);
        if (lane >= d) v += t;
    }
    if (lane == 31) ws[wid] = v;
    __syncthreads();
    if (wid == 0) {
        int w = ws[lane];
        #pragma unroll
        for (int d = 1; d < 32; d <<= 1) {
            int t = __shfl_up_sync(0xffffffffu, w, d);
            if (lane >= d) w += t;
        }
        ws[lane] = w;
    }
    __syncthreads();
    return v + (wid > 0 ? ws[wid - 1] : 0);
}

__global__ void prep_kernel(const void* r1v, const void* r2v, const void* rov,
                            const float* __restrict__ cg, int M, int out_dim) {
    __shared__ int   sp[NSORT + 1];       // ordered run-start positions
    __shared__ uint4 praw[NSORT];         // paths in position order
    __shared__ int   pro[NSORT];
    __shared__ uint4 pbin[P_SMEM];        // binned + sorted
    __shared__ int   cnt[MAX_OUT], stt[MAX_OUT], cur[MAX_OUT];
    __shared__ int   s_carry, s_is64;
    int tid = threadIdx.x, bd = blockDim.x;

    // dtype auto-detect: int64 little-endian small values -> odd words all zero
    if (tid < 32) {
        const unsigned* w = (const unsigned*)r1v;
        int nw = M < 512 ? M : 512;
        int bad = 0;
        for (int i = 1 + 2 * tid; i < nw; i += 64) bad |= (w[i] != 0u);
        unsigned any = __ballot_sync(0xffffffffu, bad != 0);
        if (tid == 0) { s_is64 = (any == 0u); s_carry = 0; }
    }
    __syncthreads();
    int is64 = s_is64;
    const int*       r132 = (const int*)r1v;  const long long* r164 = (const long long*)r1v;
    const int*       r232 = (const int*)r2v;  const long long* r264 = (const long long*)r2v;
    const int*       ro32 = (const int*)rov;  const long long* ro64 = (const long long*)rov;
    const unsigned*  cgu  = (const unsigned*)cg;
    #define IDX1(m) (is64 ? (int)r164[m] : r132[m])
    #define IDX2(m) (is64 ? (int)r264[m] : r232[m])
    #define IDXO(m) (is64 ? (int)ro64[m] : ro32[m])

    // ---- Phase A: ordered compaction of run starts (chunked block scan) ----
    for (int base = 0; base < M; base += bd) {
        int m = base + tid;
        int f = 0;
        if (m < M) {
            f = (m == 0) ||
                !(IDX1(m - 1) + 1 == IDX1(m) && IDX2(m - 1) + 1 == IDX2(m) &&
                  IDXO(m - 1) + 1 == IDXO(m) && cgu[m - 1] == cgu[m]);
        }
        int incl = block_incl_scan(f, tid);
        int pid = s_carry + incl;
        if (f && pid <= NSORT) sp[pid - 1] = m;
        __syncthreads();
        if (tid == bd - 1) s_carry = pid;   // chunk total (incl of last thread)
        __syncthreads();
    }
    int P = s_carry;
    if (P > NSORT) P = NSORT;               // safety; expected P ~ 150
    if (tid == 0) sp[P] = M;
    __syncthreads();

    // ---- Phase B: materialize paths in position order ----
    for (int p = tid; p < P; p += bd) {
        int s = sp[p];
        int deg = sp[p + 1] - s;
        praw[p] = make_uint4((unsigned)IDX1(s), (unsigned)IDX2(s),
                             cgu[s], (unsigned)deg);
        pro[p] = IDXO(s);
    }
    for (int i = tid; i < out_dim; i += bd) cnt[i] = 0;
    for (int i = tid; i < P_SMEM; i += bd) pbin[i] = make_uint4(0u, 0u, 0u, 0u);
    __syncthreads();

    // ---- Phase C: bin by ro_0, exclusive scan, scatter (all smem) ----
    for (int p = tid; p < P; p += bd) atomicAdd(&cnt[pro[p]], 1);
    __syncthreads();
    int CH = (out_dim + bd - 1) / bd;
    int cb = tid * CH;
    int local = 0;
    for (int i = 0; i < CH; i++) { int idx = cb + i; if (idx < out_dim) local += cnt[idx]; }
    int incl = block_incl_scan(local, tid);
    int run = incl - local;
    for (int i = 0; i < CH; i++) {
        int idx = cb + i;
        if (idx < out_dim) { stt[idx] = run; cur[idx] = run; run += cnt[idx]; }
    }
    __syncthreads();
    for (int p = tid; p < P; p += bd) {
        int pos = atomicAdd(&cur[pro[p]], 1);
        pbin[pos] = praw[p];
    }
    __syncthreads();

    // ---- Phase D: canonical in-bin insertion sort (smem; deg DESC, r1, r2) ----
    for (int b = tid; b < out_dim; b += bd) {
        int c0 = cnt[b];
        if (c0 > 1) {
            int s0 = stt[b];
            for (int i = 1; i < c0; i++) {
                uint4 key = pbin[s0 + i];
                int j = i - 1;
                while (j >= 0) {
                    uint4 q = pbin[s0 + j];
                    bool keyFirst = (key.w > q.w) ||
                                    (key.w == q.w && (key.x < q.x ||
                                     (key.x == q.x && key.y < q.y)));
                    if (!keyFirst) break;
                    pbin[s0 + j + 1] = q;
                    j--;
                }
                pbin[s0 + j + 1] = key;
            }
        }
    }
    __syncthreads();

    // ---- Phase E: per-column info + coalesced write-out ----
    for (int c = tid; c < out_dim; c += bd) {
        int b = c;
        while (b >= 0 && cnt[b] == 0) b--;
        uint2 info = make_uint2(0u, 0u);
        if (b >= 0) {
            int c0 = cnt[b], s0 = stt[b], ns = c - b, eff = 0;
            while (eff < c0 && (int)pbin[s0 + eff].w > ns) eff++;
            if (eff > 0)
                info = make_uint2((unsigned)s0 | ((unsigned)ns << 16), (unsigned)eff);
        }
        g_colinfo[c] = info;
    }
    for (int i = tid; i < P_SMEM; i += bd) g_paths[i] = pbin[i];
    #undef IDX1
    #undef IDX2
    #undef IDXO
}

__global__ void __launch_bounds__(TPB, OCC)
couple_kernel(const float* __restrict__ x1, const float* __restrict__ x2,
              float* __restrict__ out, int rep_dim, int out_dim, int ntiles) {
    extern __shared__ char smraw[];
    float4* x1s = (float4*)smraw;                       // rep_dim (4 rows interleaved)
    float4* x2s = x1s + rep_dim;
    uint2*  ci  = (uint2*)(x2s + rep_dim);              // out_dim
    uint4*  pts = (uint4*)(ci + ((out_dim + 1) & ~1));  // P_SMEM paths

    int tid = threadIdx.x;
    for (int i = tid; i < P_SMEM; i += TPB) pts[i] = g_paths[i];
    for (int i = tid; i < out_dim; i += TPB) ci[i] = g_colinfo[i];

    // hoisted per-thread column info; thread reads exactly the ci entries it
    // wrote (i = tid, tid+TPB) so no barrier needed here.
    int o0 = tid, o1 = tid + TPB;
    uint2 c0 = (o0 < out_dim) ? ci[o0] : make_uint2(0u, 0u);
    uint2 c1 = (o1 < out_dim) ? ci[o1] : make_uint2(0u, 0u);
    int s0 = (int)(c0.x & 0xffffu), ne0 = (int)c0.y; unsigned ns0 = c0.x >> 16;
    int s1 = (int)(c1.x & 0xffffu), ne1 = (int)c1.y; unsigned ns1 = c1.x >> 16;

    for (int t = blockIdx.x; t < ntiles; t += gridDim.x) {
        __syncthreads();   // prior tile fully consumed (and 1st iter: pts ready)
        {
            const float* a0 = x1 + (size_t)t * RPT * rep_dim;
            const float* b0 = x2 + (size_t)t * RPT * rep_dim;
            for (int i = tid; i < rep_dim; i += TPB) {
                x1s[i] = make_float4(a0[i], a0[i + rep_dim],
                                     a0[i + 2 * rep_dim], a0[i + 3 * rep_dim]);
                x2s[i] = make_float4(b0[i], b0[i + rep_dim],
                                     b0[i + 2 * rep_dim], b0[i + 3 * rep_dim]);
            }
        }
        __syncthreads();

        float4 acc0 = make_float4(0.f, 0.f, 0.f, 0.f);
        float4 acc1 = make_float4(0.f, 0.f, 0.f, 0.f);
        #pragma unroll 2
        for (int j = 0; j < ne0; j++) {
            uint4 p = pts[s0 + j];               // warp-uniform: broadcast
            float cgv = __uint_as_float(p.z);
            float4 A = x1s[p.x + ns0];           // lane-consecutive: conflict-free
            float4 B = x2s[p.y + ns0];
            acc0.x = fmaf(A.x * B.x, cgv, acc0.x);
            acc0.y = fmaf(A.y * B.y, cgv, acc0.y);
            acc0.z = fmaf(A.z * B.z, cgv, acc0.z);
            acc0.w = fmaf(A.w * B.w, cgv, acc0.w);
        }
        #pragma unroll 2
        for (int j = 0; j < ne1; j++) {
            uint4 p = pts[s1 + j];
            float cgv = __uint_as_float(p.z);
            float4 A = x1s[p.x + ns1];
            float4 B = x2s[p.y + ns1];
            acc1.x = fmaf(A.x * B.x, cgv, acc1.x);
            acc1.y = fmaf(A.y * B.y, cgv, acc1.y);
            acc1.z = fmaf(A.z * B.z, cgv, acc1.z);
            acc1.w = fmaf(A.w * B.w, cgv, acc1.w);
        }
        int r = t * RPT;
        if (o0 < out_dim) {
            float* ob = out + (size_t)r * out_dim + o0;
            ob[0] = acc0.x; ob[out_dim] = acc0.y;
            ob[2 * (size_t)out_dim] = acc0.z; ob[3 * (size_t)out_dim] = acc0.w;
        }
        if (o1 < out_dim) {
            float* ob = out + (size_t)r * out_dim + o1;
            ob[0] = acc1.x; ob[out_dim] = acc1.y;
            ob[2 * (size_t)out_dim] = acc1.z; ob[3 * (size_t)out_dim] = acc1.w;
        }
        // generic fallback for out_dim > 2*TPB (not taken for this shape)
        for (int obase = 2 * TPB; obase < out_dim; obase += TPB) {
            int o = obase + tid;
            if (o < out_dim) {
                uint2 c = ci[o];
                int s = (int)(c.x & 0xffffu), ne = (int)c.y;
                unsigned ns = c.x >> 16;
                float4 acc = make_float4(0.f, 0.f, 0.f, 0.f);
                for (int j = 0; j < ne; j++) {
                    uint4 p = pts[s + j];
                    float cgv = __uint_as_float(p.z);
                    float4 A = x1s[p.x + ns];
                    float4 B = x2s[p.y + ns];
                    acc.x = fmaf(A.x * B.x, cgv, acc.x);
                    acc.y = fmaf(A.y * B.y, cgv, acc.y);
                    acc.z = fmaf(A.z * B.z, cgv, acc.z);
                    acc.w = fmaf(A.w * B.w, cgv, acc.w);
                }
                float* ob = out + (size_t)r * out_dim + o;
                ob[0] = acc.x; ob[out_dim] = acc.y;
                ob[2 * (size_t)out_dim] = acc.z; ob[3 * (size_t)out_dim] = acc.w;
            }
        }
    }
}

extern "C" void kernel_launch(void* const* d_in, const int* in_sizes, int n_in,
                              void* d_out, int out_size) {
    const float* x1 = (const float*)d_in[0];
    const float* x2 = (const float*)d_in[1];
    const float* cg = (const float*)d_in[2];
    const void*  r1 = d_in[3];
    const void*  r2 = d_in[4];
    const void*  ro = d_in[5];
    int M = in_sizes[2];
    int rep_dim = in_sizes[0] / N_BATCH;
    int out_dim = out_size / N_BATCH;
    int ntiles  = N_BATCH / RPT;

    prep_kernel<<<1, 1024>>>(r1, r2, ro, cg, M, out_dim);

    size_t smem = (size_t)rep_dim * 32 + (size_t)((out_dim + 1) & ~1) * 8
                + (size_t)P_SMEM * 16;
    cudaFuncSetAttribute(couple_kernel,
                         cudaFuncAttributeMaxDynamicSharedMemorySize, 220 * 1024);
    int grid = NSM * OCC;
    if (grid > ntiles) grid = ntiles;
    couple_kernel<<<grid, TPB, smem>>>(x1, x2, (float*)d_out,
                                       rep_dim, out_dim, ntiles);
}

// round 10
// speedup vs baseline: 1.1970x; 1.0946x over previous
#include <cuda_runtime.h>

// CGCoupler: out[n, ro[m]] += x1[n, r1[m]] * x2[n, r2[m]] * cg[m]
//
// Paths: index arrays are path-major runs (r1/r2/ro consecutive, cg equal) over
// a dense channel dim ns=0..deg-1. Run starts partition [0,M):
// deg_i = start_{i+1} - start_i.
// prep (1 CTA, smem-resident, SINGLE block scan): each thread owns a contiguous
//   chunk of M, counts run starts, one block scan gives ordered offsets, second
//   (L1-hot) pass writes positions. Then bin by ro_0, prefix scan, scatter,
//   canonical in-bin insertion sort (deg desc, r1 asc, r2 asc) in smem, one
//   coalesced write-out of g_paths (zero-padded) + g_colinfo.
// couple (persistent, 4 CTAs/SM -- no spills): thread owns 2 columns
//   (tid, tid+TPB); x tiles staged 4-rows-interleaved as float4 so gathers are
//   lane-consecutive LDS.128 (conflict-free); path records broadcast from smem.

#define N_BATCH 16384
#define RPT     4
#define TPB     320
#define OCC     4
#define NSM     148
#define MAX_OUT 2048
#define P_SMEM  512
#define NSORT   512

__device__ uint4 g_paths[P_SMEM];     // binned + canonically sorted {r1,r2,cg,deg}
__device__ uint2 g_colinfo[MAX_OUT];  // {start | ns<<16, eff}

__device__ __forceinline__ int block_incl_scan(int v, int tid) {
    __shared__ int ws[32];
    int lane = tid & 31, wid = tid >> 5;
    __syncthreads();
    #pragma unroll
    for (int d = 1; d < 32; d <<= 1) {
        int t = __shfl_up_sync(0xffffffffu, v, d);
        if (lane >= d) v += t;
    }
    if (lane == 31) ws[wid] = v;
    __syncthreads();
    if (wid == 0) {
        int w = ws[lane];
        #pragma unroll
        for (int d = 1; d < 32; d <<= 1) {
            int t = __shfl_up_sync(0xffffffffu, w, d);
            if (lane >= d) w += t;
        }
        ws[lane] = w;
    }
    __syncthreads();
    return v + (wid > 0 ? ws[wid - 1] : 0);
}

__global__ void prep_kernel(const void* r1v, const void* r2v, const void* rov,
                            const float* __restrict__ cg, int M, int out_dim) {
    __shared__ int   sp[NSORT + 1];       // ordered run-start positions
    __shared__ uint4 praw[NSORT];         // paths in position order
    __shared__ int   pro[NSORT];
    __shared__ uint4 pbin[P_SMEM];        // binned + sorted
    __shared__ int   cnt[MAX_OUT], stt[MAX_OUT], cur[MAX_OUT];
    __shared__ int   s_is64, s_np;
    int tid = threadIdx.x, bd = blockDim.x;

    // dtype auto-detect: int64 little-endian small values -> odd words all zero
    if (tid < 32) {
        const unsigned* w = (const unsigned*)r1v;
        int nw = M < 512 ? M : 512;
        int bad = 0;
        for (int i = 1 + 2 * tid; i < nw; i += 64) bad |= (w[i] != 0u);
        unsigned any = __ballot_sync(0xffffffffu, bad != 0);
        if (tid == 0) s_is64 = (any == 0u);
    }
    __syncthreads();
    int is64 = s_is64;
    const int*       r132 = (const int*)r1v;  const long long* r164 = (const long long*)r1v;
    const int*       r232 = (const int*)r2v;  const long long* r264 = (const long long*)r2v;
    const int*       ro32 = (const int*)rov;  const long long* ro64 = (const long long*)rov;
    const unsigned*  cgu  = (const unsigned*)cg;
    #define IDX1(m) (is64 ? (int)r164[m] : r132[m])
    #define IDX2(m) (is64 ? (int)r264[m] : r232[m])
    #define IDXO(m) (is64 ? (int)ro64[m] : ro32[m])
    #define ISSTART(m) ((m) == 0 || \
        !(IDX1((m) - 1) + 1 == IDX1(m) && IDX2((m) - 1) + 1 == IDX2(m) && \
          IDXO((m) - 1) + 1 == IDXO(m) && cgu[(m) - 1] == cgu[m]))

    // ---- Phase A: ordered compaction of run starts, ONE block scan ----
    int C = (M + bd - 1) / bd;
    int beg = tid * C;
    int end = beg + C; if (end > M) end = M;
    int cl = 0;
    for (int m = beg; m < end; m++) cl += ISSTART(m);
    int incl = block_incl_scan(cl, tid);
    int off = incl - cl;
    for (int m = beg; m < end; m++)            // reloads hit L1 (hot)
        if (ISSTART(m)) { if (off < NSORT) sp[off] = m; off++; }
    if (tid == bd - 1) s_np = incl;
    __syncthreads();
    int P = s_np;
    if (P > NSORT) P = NSORT;                  // safety; expected P ~ 150
    if (tid == 0) sp[P] = M;
    __syncthreads();

    // ---- Phase B: materialize paths in position order ----
    for (int p = tid; p < P; p += bd) {
        int s = sp[p];
        int deg = sp[p + 1] - s;
        praw[p] = make_uint4((unsigned)IDX1(s), (unsigned)IDX2(s),
                             cgu[s], (unsigned)deg);
        pro[p] = IDXO(s);
    }
    for (int i = tid; i < out_dim; i += bd) cnt[i] = 0;
    for (int i = tid; i < P_SMEM; i += bd) pbin[i] = make_uint4(0u, 0u, 0u, 0u);
    __syncthreads();

    // ---- Phase C: bin by ro_0, exclusive scan, scatter (all smem) ----
    for (int p = tid; p < P; p += bd) atomicAdd(&cnt[pro[p]], 1);
    __syncthreads();
    int CH = (out_dim + bd - 1) / bd;
    int cb = tid * CH;
    int local = 0;
    for (int i = 0; i < CH; i++) { int idx = cb + i; if (idx < out_dim) local += cnt[idx]; }
    int incl2 = block_incl_scan(local, tid);
    int run = incl2 - local;
    for (int i = 0; i < CH; i++) {
        int idx = cb + i;
        if (idx < out_dim) { stt[idx] = run; cur[idx] = run; run += cnt[idx]; }
    }
    __syncthreads();
    for (int p = tid; p < P; p += bd) {
        int pos = atomicAdd(&cur[pro[p]], 1);
        pbin[pos] = praw[p];
    }
    __syncthreads();

    // ---- Phase D: canonical in-bin insertion sort (smem; deg DESC, r1, r2) ----
    for (int b = tid; b < out_dim; b += bd) {
        int c0 = cnt[b];
        if (c0 > 1) {
            int s0 = stt[b];
            for (int i = 1; i < c0; i++) {
                uint4 key = pbin[s0 + i];
                int j = i - 1;
                while (j >= 0) {
                    uint4 q = pbin[s0 + j];
                    bool keyFirst = (key.w > q.w) ||
                                    (key.w == q.w && (key.x < q.x ||
                                     (key.x == q.x && key.y < q.y)));
                    if (!keyFirst) break;
                    pbin[s0 + j + 1] = q;
                    j--;
                }
                pbin[s0 + j + 1] = key;
            }
        }
    }
    __syncthreads();

    // ---- Phase E: per-column info + coalesced write-out ----
    for (int c = tid; c < out_dim; c += bd) {
        int b = c;
        while (b >= 0 && cnt[b] == 0) b--;
        uint2 info = make_uint2(0u, 0u);
        if (b >= 0) {
            int c0 = cnt[b], s0 = stt[b], ns = c - b, eff = 0;
            while (eff < c0 && (int)pbin[s0 + eff].w > ns) eff++;
            if (eff > 0)
                info = make_uint2((unsigned)s0 | ((unsigned)ns << 16), (unsigned)eff);
        }
        g_colinfo[c] = info;
    }
    for (int i = tid; i < P_SMEM; i += bd) g_paths[i] = pbin[i];
    #undef ISSTART
    #undef IDX1
    #undef IDX2
    #undef IDXO
}

__global__ void __launch_bounds__(TPB, OCC)
couple_kernel(const float* __restrict__ x1, const float* __restrict__ x2,
              float* __restrict__ out, int rep_dim, int out_dim, int ntiles) {
    extern __shared__ char smraw[];
    float4* x1s = (float4*)smraw;                       // rep_dim (4 rows interleaved)
    float4* x2s = x1s + rep_dim;
    uint2*  ci  = (uint2*)(x2s + rep_dim);              // out_dim
    uint4*  pts = (uint4*)(ci + ((out_dim + 1) & ~1));  // P_SMEM paths

    int tid = threadIdx.x;
    for (int i = tid; i < P_SMEM; i += TPB) pts[i] = g_paths[i];
    for (int i = tid; i < out_dim; i += TPB) ci[i] = g_colinfo[i];

    // hoisted per-thread column info; thread reads exactly the ci entries it
    // wrote (i = tid, tid+TPB) so no barrier needed here.
    int o0 = tid, o1 = tid + TPB;
    uint2 c0 = (o0 < out_dim) ? ci[o0] : make_uint2(0u, 0u);
    uint2 c1 = (o1 < out_dim) ? ci[o1] : make_uint2(0u, 0u);
    int s0 = (int)(c0.x & 0xffffu), ne0 = (int)c0.y; unsigned ns0 = c0.x >> 16;
    int s1 = (int)(c1.x & 0xffffu), ne1 = (int)c1.y; unsigned ns1 = c1.x >> 16;

    for (int t = blockIdx.x; t < ntiles; t += gridDim.x) {
        __syncthreads();   // prior tile fully consumed (and 1st iter: pts ready)
        {
            const float* a0 = x1 + (size_t)t * RPT * rep_dim;
            const float* b0 = x2 + (size_t)t * RPT * rep_dim;
            for (int i = tid; i < rep_dim; i += TPB) {
                x1s[i] = make_float4(a0[i], a0[i + rep_dim],
                                     a0[i + 2 * rep_dim], a0[i + 3 * rep_dim]);
                x2s[i] = make_float4(b0[i], b0[i + rep_dim],
                                     b0[i + 2 * rep_dim], b0[i + 3 * rep_dim]);
            }
        }
        __syncthreads();

        float4 acc0 = make_float4(0.f, 0.f, 0.f, 0.f);
        float4 acc1 = make_float4(0.f, 0.f, 0.f, 0.f);
        #pragma unroll 2
        for (int j = 0; j < ne0; j++) {
            uint4 p = pts[s0 + j];               // warp-uniform: broadcast
            float cgv = __uint_as_float(p.z);
            float4 A = x1s[p.x + ns0];           // lane-consecutive: conflict-free
            float4 B = x2s[p.y + ns0];
            acc0.x = fmaf(A.x * B.x, cgv, acc0.x);
            acc0.y = fmaf(A.y * B.y, cgv, acc0.y);
            acc0.z = fmaf(A.z * B.z, cgv, acc0.z);
            acc0.w = fmaf(A.w * B.w, cgv, acc0.w);
        }
        #pragma unroll 2
        for (int j = 0; j < ne1; j++) {
            uint4 p = pts[s1 + j];
            float cgv = __uint_as_float(p.z);
            float4 A = x1s[p.x + ns1];
            float4 B = x2s[p.y + ns1];
            acc1.x = fmaf(A.x * B.x, cgv, acc1.x);
            acc1.y = fmaf(A.y * B.y, cgv, acc1.y);
            acc1.z = fmaf(A.z * B.z, cgv, acc1.z);
            acc1.w = fmaf(A.w * B.w, cgv, acc1.w);
        }
        int r = t * RPT;
        if (o0 < out_dim) {
            float* ob = out + (size_t)r * out_dim + o0;
            ob[0] = acc0.x; ob[out_dim] = acc0.y;
            ob[2 * (size_t)out_dim] = acc0.z; ob[3 * (size_t)out_dim] = acc0.w;
        }
        if (o1 < out_dim) {
            float* ob = out + (size_t)r * out_dim + o1;
            ob[0] = acc1.x; ob[out_dim] = acc1.y;
            ob[2 * (size_t)out_dim] = acc1.z; ob[3 * (size_t)out_dim] = acc1.w;
        }
        // generic fallback for out_dim > 2*TPB (not taken for this shape)
        for (int obase = 2 * TPB; obase < out_dim; obase += TPB) {
            int o = obase + tid;
            if (o < out_dim) {
                uint2 c = ci[o];
                int s = (int)(c.x & 0xffffu), ne = (int)c.y;
                unsigned ns = c.x >> 16;
                float4 acc = make_float4(0.f, 0.f, 0.f, 0.f);
                for (int j = 0; j < ne; j++) {
                    uint4 p = pts[s + j];
                    float cgv = __uint_as_float(p.z);
                    float4 A = x1s[p.x + ns];
                    float4 B = x2s[p.y + ns];
                    acc.x = fmaf(A.x * B.x, cgv, acc.x);
                    acc.y = fmaf(A.y * B.y, cgv, acc.y);
                    acc.z = fmaf(A.z * B.z, cgv, acc.z);
                    acc.w = fmaf(A.w * B.w, cgv, acc.w);
                }
                float* ob = out + (size_t)r * out_dim + o;
                ob[0] = acc.x; ob[out_dim] = acc.y;
                ob[2 * (size_t)out_dim] = acc.z; ob[3 * (size_t)out_dim] = acc.w;
            }
        }
    }
}

extern "C" void kernel_launch(void* const* d_in, const int* in_sizes, int n_in,
                              void* d_out, int out_size) {
    const float* x1 = (const float*)d_in[0];
    const float* x2 = (const float*)d_in[1];
    const float* cg = (const float*)d_in[2];
    const void*  r1 = d_in[3];
    const void*  r2 = d_in[4];
    const void*  ro = d_in[5];
    int M = in_sizes[2];
    int rep_dim = in_sizes[0] / N_BATCH;
    int out_dim = out_size / N_BATCH;
    int ntiles  = N_BATCH / RPT;

    prep_kernel<<<1, 1024>>>(r1, r2, ro, cg, M, out_dim);

    size_t smem = (size_t)rep_dim * 32 + (size_t)((out_dim + 1) & ~1) * 8
                + (size_t)P_SMEM * 16;
    cudaFuncSetAttribute(couple_kernel,
                         cudaFuncAttributeMaxDynamicSharedMemorySize, 220 * 1024);
    int grid = NSM * OCC;
    if (grid > ntiles) grid = ntiles;
    couple_kernel<<<grid, TPB, smem>>>(x1, x2, (float*)d_out,
                                       rep_dim, out_dim, ntiles);
}